// round 1
// baseline (speedup 1.0000x reference)
#include <cuda_runtime.h>
#include <math.h>

#define NPIX (128*32*16*16)   // 1048576
#define VV 4096

struct Pair { float v; int i; };

// ---------------- static device scratch (no allocations allowed) ----------------
__device__ float g_frest[NPIX];
__device__ float g_rsmall[128*32*169];
__device__ float g_hsmall[NPIX];
__device__ float g_hup[NPIX];
__device__ float g_esq[VV];
__device__ float g_bicW[9*16*4];
__device__ int   g_bicI[9*16*4];
__device__ Pair  g_part[32768*32];
__device__ float g_loss;

// ---------------- bicubic tap tables (double math, matches numpy/torch) ----------------
__global__ void taps_kernel()
{
    int t = blockIdx.x * blockDim.x + threadIdx.x;
    if (t >= 144) return;               // 9 stages x 16 output rows
    int si = t >> 4, o = t & 15;
    const int pns[10] = {1,2,3,4,5,6,8,10,13,16};
    int in_s = pns[si];
    double src = (o + 0.5) * (double)in_s / 16.0 - 0.5;
    double fl = floor(src);
    const double a = -0.75;
    for (int tt = 0; tt < 4; tt++) {
        double x = fabs(src - (fl + (double)(tt - 1)));
        double w;
        if (x <= 1.0)      w = (a + 2.0)*x*x*x - (a + 3.0)*x*x + 1.0;
        else if (x < 2.0)  w = a*x*x*x - 5.0*a*x*x + 8.0*a*x - 4.0*a;
        else               w = 0.0;
        int idx = (int)fl + (tt - 1);
        if (idx < 0) idx = 0;
        if (idx > in_s - 1) idx = in_s - 1;
        g_bicW[(si*16 + o)*4 + tt] = (float)w;
        g_bicI[(si*16 + o)*4 + tt] = idx;
    }
}

// ---------------- e_sq = sum_c emb^2 ----------------
__global__ void esq_kernel(const float* __restrict__ emb)
{
    int v = blockIdx.x * blockDim.x + threadIdx.x;
    if (v < VV) {
        float s = 0.f;
        #pragma unroll
        for (int c = 0; c < 32; c++) { float e = emb[v*32 + c]; s = fmaf(e, e, s); }
        g_esq[v] = s;
    }
}

// ---------------- init: f_rest = f, f_hat = 0, loss = 0 ----------------
__global__ void init_kernel(const float* __restrict__ f, float* __restrict__ out)
{
    int i = blockIdx.x * blockDim.x + threadIdx.x;
    if (i < NPIX) { g_frest[i] = f[i]; out[i] = 0.f; }
    if (i == 0) g_loss = 0.f;
}

// ---------------- area downsample: f_rest[B,C,16,16] -> rs[B,C,pn,pn] ----------------
__global__ void down_kernel(const float* __restrict__ fr, float* __restrict__ rs, int pn)
{
    int i = blockIdx.x * blockDim.x + threadIdx.x;
    int pp = pn * pn;
    int total = 128*32*pp;
    if (i >= total) return;
    int ox = i % pn; int t = i / pn;
    int oy = t % pn; int bc = t / pn;
    int sy0 = (oy*16)/pn,      sy1 = ((oy+1)*16 + pn - 1)/pn;
    int sx0 = (ox*16)/pn,      sx1 = ((ox+1)*16 + pn - 1)/pn;
    const float* base = fr + bc*256;
    float s = 0.f;
    for (int y = sy0; y < sy1; y++)
        for (int x = sx0; x < sx1; x++)
            s += base[y*16 + x];
    rs[i] = s / (float)((sy1 - sy0)*(sx1 - sx0));
}

// ---------------- NN search: 128-vec x 128-code register-tiled GEMM + running argmin ----
// grid.x = N/128 (vector tiles), grid.y = code split; each block scans cpb codes.
__global__ __launch_bounds__(256, 1) void nn_kernel(const float* __restrict__ rest,
                                                    const float* __restrict__ emb,
                                                    int pp, int cpb)
{
    __shared__ __align__(16) float sR[32][128];
    __shared__ __align__(16) float sC[32][128];
    int tid = threadIdx.x;
    int n0 = blockIdx.x << 7;
    int cbase = blockIdx.y * cpb;

    // load + transpose rest tile: sR[c][v]
    for (int j = tid; j < 4096; j += 256) {
        int v = j >> 5, c = j & 31;
        int n = n0 + v;
        int b = n / pp, rem = n - b*pp;
        sR[c][v] = rest[(b*32 + c)*pp + rem];
    }

    float best[8]; int bidx[8];
    #pragma unroll
    for (int i = 0; i < 8; i++) { best[i] = 3.4e38f; bidx[i] = 0; }
    int tx = tid & 15, ty = tid >> 4;
    int nch = cpb >> 7;

    for (int ch = 0; ch < nch; ch++) {
        __syncthreads();
        int cb = cbase + (ch << 7);
        const float* ebase = emb + (size_t)cb * 32;
        for (int j = tid; j < 4096; j += 256) {
            int cl = j >> 5, k = j & 31;
            sC[k][cl] = ebase[cl*32 + k];
        }
        __syncthreads();

        float acc[8][8];
        #pragma unroll
        for (int i = 0; i < 8; i++)
            #pragma unroll
            for (int j2 = 0; j2 < 8; j2++) acc[i][j2] = 0.f;

        #pragma unroll 4
        for (int k = 0; k < 32; k++) {
            float4 a0 = *(const float4*)&sR[k][ty*8];
            float4 a1 = *(const float4*)&sR[k][ty*8 + 4];
            float4 b0 = *(const float4*)&sC[k][tx*8];
            float4 b1 = *(const float4*)&sC[k][tx*8 + 4];
            float av[8] = {a0.x,a0.y,a0.z,a0.w,a1.x,a1.y,a1.z,a1.w};
            float bv[8] = {b0.x,b0.y,b0.z,b0.w,b1.x,b1.y,b1.z,b1.w};
            #pragma unroll
            for (int i = 0; i < 8; i++)
                #pragma unroll
                for (int j2 = 0; j2 < 8; j2++)
                    acc[i][j2] = fmaf(av[i], bv[j2], acc[i][j2]);
        }

        #pragma unroll
        for (int j2 = 0; j2 < 8; j2++) {
            int code = cb + tx*8 + j2;
            float es = g_esq[code];
            #pragma unroll
            for (int i = 0; i < 8; i++) {
                float s = es - 2.0f * acc[i][j2];
                if (s < best[i]) { best[i] = s; bidx[i] = code; }  // codes ascend -> first-min kept
            }
        }
    }

    __syncthreads();
    Pair* pr = (Pair*)sC;   // reuse sC (16KB = 128*16 pairs)
    #pragma unroll
    for (int i = 0; i < 8; i++) {
        pr[(ty*8 + i)*16 + tx].v = best[i];
        pr[(ty*8 + i)*16 + tx].i = bidx[i];
    }
    __syncthreads();
    if (tid < 128) {
        Pair p = pr[tid*16];
        #pragma unroll
        for (int t2 = 1; t2 < 16; t2++) {
            Pair q = pr[tid*16 + t2];
            if (q.v < p.v || (q.v == p.v && q.i < p.i)) p = q;
        }
        g_part[(size_t)(n0 + tid)*32 + blockIdx.y] = p;
    }
}

// ---------------- final argmin across splits + write idx + gather emb -> h_small -------
// one warp per vector: lanes < split reduce partials; then all 32 lanes gather one channel
__global__ void reduce_gather_kernel(const float* __restrict__ emb,
                                     float* __restrict__ outIdx,
                                     float* __restrict__ hsm,
                                     int pp, int split)
{
    int lane = threadIdx.x & 31;
    int n = (blockIdx.x << 3) + (threadIdx.x >> 5);
    float v = 3.4e38f; int bi = 0x7fffffff;
    if (lane < split) { Pair p = g_part[(size_t)n*32 + lane]; v = p.v; bi = p.i; }
    #pragma unroll
    for (int off = 16; off; off >>= 1) {
        float ov = __shfl_down_sync(0xffffffffu, v, off);
        int   oi = __shfl_down_sync(0xffffffffu, bi, off);
        if (ov < v || (ov == v && oi < bi)) { v = ov; bi = oi; }
    }
    int idx = __shfl_sync(0xffffffffu, bi, 0);
    if (lane == 0) outIdx[n] = (float)idx;
    int b = n / pp, rem = n - b*pp;
    hsm[(b*32 + lane)*pp + rem] = emb[idx*32 + lane];
}

// ---------------- bicubic upsample: h_small[B,C,pn,pn] -> h_up[B,C,16,16] -------------
__global__ void up_kernel(const float* __restrict__ hs, float* __restrict__ hu,
                          int si, int pn)
{
    int i = blockIdx.x * blockDim.x + threadIdx.x;
    if (i >= NPIX) return;
    int ox = i & 15; int oy = (i >> 4) & 15; int bc = i >> 8;
    const float* base = hs + bc * pn * pn;
    const float* Wy = g_bicW + (si*16 + oy)*4;
    const int*   Iy = g_bicI + (si*16 + oy)*4;
    const float* Wx = g_bicW + (si*16 + ox)*4;
    const int*   Ix = g_bicI + (si*16 + ox)*4;
    float acc = 0.f;
    #pragma unroll
    for (int txp = 0; txp < 4; txp++) {
        float col = 0.f;
        #pragma unroll
        for (int typ = 0; typ < 4; typ++)
            col = fmaf(Wy[typ], base[Iy[typ]*pn + Ix[txp]], col);
        acc = fmaf(Wx[txp], col, acc);
    }
    hu[i] = acc;
}

// ---------------- Phi conv (3x3, 32->32) + residual update + loss --------------------
// one block per image b; smem = input tile (32x18x18, zero halo) + weights (32x32x9)
__global__ __launch_bounds__(256, 1) void conv_update_kernel(
        const float* __restrict__ hup, const float* __restrict__ W,
        const float* __restrict__ bias, const float* __restrict__ f,
        float* __restrict__ fhat, float* __restrict__ frest)
{
    extern __shared__ float sm[];
    float* sIn = sm;            // 32*324
    float* sW  = sm + 32*324;   // 9216
    int b = blockIdx.x, tid = threadIdx.x;

    for (int j = tid; j < 32*324; j += 256) {
        int x = j % 18; int t = j / 18; int y = t % 18; int c = t / 18;
        float v = 0.f;
        if (x >= 1 && x <= 16 && y >= 1 && y <= 16)
            v = hup[((b*32 + c)*16 + (y - 1))*16 + (x - 1)];
        sIn[j] = v;
    }
    for (int j = tid; j < 9216; j += 256) sW[j] = W[j];
    __syncthreads();

    int cog = tid >> 5;       // warp-uniform: co = cog*4 .. +3
    int pxg = tid & 31;       // 8 pixels each
    int p0 = pxg << 3;
    int y = p0 >> 4, x0 = p0 & 15;

    float acc[4][8];
    #pragma unroll
    for (int q = 0; q < 4; q++)
        #pragma unroll
        for (int m = 0; m < 8; m++) acc[q][m] = 0.f;

    for (int ci = 0; ci < 32; ci++) {
        const float* inC = sIn + ci*324;
        const float* wC  = sW + (cog*4)*288 + ci*9;
        #pragma unroll
        for (int dy = 0; dy < 3; dy++) {
            float row[10];
            const float* r = inC + (y + dy)*18 + x0;
            #pragma unroll
            for (int j = 0; j < 10; j++) row[j] = r[j];
            #pragma unroll
            for (int dx = 0; dx < 3; dx++) {
                float w0 = wC[0*288 + dy*3 + dx];
                float w1 = wC[1*288 + dy*3 + dx];
                float w2 = wC[2*288 + dy*3 + dx];
                float w3 = wC[3*288 + dy*3 + dx];
                #pragma unroll
                for (int m = 0; m < 8; m++) {
                    float iv = row[dx + m];
                    acc[0][m] = fmaf(w0, iv, acc[0][m]);
                    acc[1][m] = fmaf(w1, iv, acc[1][m]);
                    acc[2][m] = fmaf(w2, iv, acc[2][m]);
                    acc[3][m] = fmaf(w3, iv, acc[3][m]);
                }
            }
        }
    }

    float lsum = 0.f;
    #pragma unroll
    for (int q = 0; q < 4; q++) {
        int co = cog*4 + q;
        float bv = bias[co];
        #pragma unroll
        for (int m = 0; m < 8; m++) {
            int px = x0 + m;
            int gi = ((b*32 + co)*16 + y)*16 + px;
            float hv = sIn[co*324 + (y + 1)*18 + (px + 1)];
            float h = hv*0.5f + (acc[q][m] + bv)*0.5f;   // h*(1-r) + conv*r, r=0.5
            float fh = fhat[gi] + h;
            fhat[gi] = fh;
            frest[gi] -= h;
            float d = fh - f[gi];
            lsum += d*d;
        }
    }
    #pragma unroll
    for (int off = 16; off; off >>= 1) lsum += __shfl_down_sync(0xffffffffu, lsum, off);
    if ((tid & 31) == 0) atomicAdd(&g_loss, lsum);
}

__global__ void fin_kernel(float* __restrict__ out)
{
    if (threadIdx.x == 0)
        out[NPIX] = g_loss * 1.25f / 10.0f / 1048576.0f;
}

// =====================================================================================
extern "C" void kernel_launch(void* const* d_in, const int* in_sizes, int n_in,
                              void* d_out, int out_size)
{
    const float* f    = (const float*)d_in[0];
    const float* emb  = (const float*)d_in[1];
    const float* phiW = (const float*)d_in[2];
    const float* phib = (const float*)d_in[3];
    float* out = (float*)d_out;

    float *frest, *rsmall, *hsm, *hup;
    cudaGetSymbolAddress((void**)&frest,  g_frest);
    cudaGetSymbolAddress((void**)&rsmall, g_rsmall);
    cudaGetSymbolAddress((void**)&hsm,    g_hsmall);
    cudaGetSymbolAddress((void**)&hup,    g_hup);

    static const int pns[10] = {1,2,3,4,5,6,8,10,13,16};

    // phi index map: replicate np.linspace + argmin(|ticks - si/9|) in exact doubles
    int kmap[10];
    {
        double start = 1.0/(3.0*4.0);
        double stop  = 1.0 - 1.0/(3.0*4.0);
        double step  = (stop - start)/3.0;
        double ticks[4];
        for (int i2 = 0; i2 < 4; i2++) ticks[i2] = (double)i2*step + start;
        ticks[3] = stop;
        for (int si = 0; si < 10; si++) {
            double s = (double)si / 9.0;
            int bk = 0; double bvv = fabs(ticks[0] - s);
            for (int i2 = 1; i2 < 4; i2++) {
                double vv = fabs(ticks[i2] - s);
                if (vv < bvv) { bvv = vv; bk = i2; }
            }
            kmap[si] = bk;
        }
    }

    int convSmem = (32*324 + 9216) * (int)sizeof(float);
    cudaFuncSetAttribute(conv_update_kernel,
                         cudaFuncAttributeMaxDynamicSharedMemorySize, convSmem);

    taps_kernel<<<1, 160>>>();
    esq_kernel<<<16, 256>>>(emb);
    init_kernel<<<NPIX/256, 256>>>(f, out);

    float* idxbase = out + NPIX + 1;
    int idxoff = 0;
    for (int si = 0; si < 10; si++) {
        int pn = pns[si], pp = pn*pn;
        int N = 128*pp;
        const float* rest;
        if (si < 9) {
            int tot = 128*32*pp;
            down_kernel<<<(tot + 255)/256, 256>>>(frest, rsmall, pn);
            rest = rsmall;
        } else {
            rest = frest;
        }
        int nvb = N/128;
        int split = 1;
        while (split < 32 && nvb*split < 256) split <<= 1;   // target >=256 blocks
        dim3 g(nvb, split);
        nn_kernel<<<g, 256>>>(rest, emb, pp, VV/split);
        reduce_gather_kernel<<<N/8, 256>>>(emb, idxbase + idxoff, hsm, pp, split);

        const float* convin;
        if (si < 9) {
            up_kernel<<<NPIX/256, 256>>>(hsm, hup, si, pn);
            convin = hup;
        } else {
            convin = hsm;
        }
        conv_update_kernel<<<128, 256, convSmem>>>(convin,
                phiW + kmap[si]*32*32*9, phib + kmap[si]*32, f, out, frest);
        idxoff += N;
    }
    fin_kernel<<<1, 32>>>(out);
}

// round 2
// speedup vs baseline: 1.0077x; 1.0077x over previous
#include <cuda_runtime.h>
#include <math.h>

#define NPIX (128*32*16*16)   // 1048576
#define VV 4096

struct Pair { float v; int i; };

// ---------------- static device scratch (no allocations allowed) ----------------
__device__ float g_frest[NPIX];
__device__ float g_rsmall[128*32*169];
__device__ float g_hsmall[NPIX];
__device__ float g_esq[VV];
__device__ float g_bicW[9*16*4];
__device__ int   g_bicI[9*16*4];
__device__ Pair  g_part[32768*32];
__device__ float g_loss;

// ---------------- packed f32x2 FMA helpers ----------------
__device__ __forceinline__ void ffma2(unsigned long long &d, unsigned long long a,
                                      unsigned long long b)
{
    asm("fma.rn.f32x2 %0, %1, %2, %0;" : "+l"(d) : "l"(a), "l"(b));
}
__device__ __forceinline__ unsigned long long dup2(float a)
{
    unsigned long long r;
    asm("mov.b64 %0, {%1, %1};" : "=l"(r) : "f"(a));
    return r;
}
__device__ __forceinline__ void unpack2(unsigned long long p, float &lo, float &hi)
{
    asm("mov.b64 {%0, %1}, %2;" : "=f"(lo), "=f"(hi) : "l"(p));
}

// ---------------- bicubic tap tables (double math, matches numpy/torch) ------------
__global__ void taps_kernel()
{
    int t = blockIdx.x * blockDim.x + threadIdx.x;
    if (t >= 144) return;               // 9 stages x 16 output rows
    int si = t >> 4, o = t & 15;
    const int pns[10] = {1,2,3,4,5,6,8,10,13,16};
    int in_s = pns[si];
    double src = (o + 0.5) * (double)in_s / 16.0 - 0.5;
    double fl = floor(src);
    const double a = -0.75;
    for (int tt = 0; tt < 4; tt++) {
        double x = fabs(src - (fl + (double)(tt - 1)));
        double w;
        if (x <= 1.0)      w = (a + 2.0)*x*x*x - (a + 3.0)*x*x + 1.0;
        else if (x < 2.0)  w = a*x*x*x - 5.0*a*x*x + 8.0*a*x - 4.0*a;
        else               w = 0.0;
        int idx = (int)fl + (tt - 1);
        if (idx < 0) idx = 0;
        if (idx > in_s - 1) idx = in_s - 1;
        g_bicW[(si*16 + o)*4 + tt] = (float)w;
        g_bicI[(si*16 + o)*4 + tt] = idx;
    }
}

// ---------------- e_sq = sum_c emb^2 ----------------
__global__ void esq_kernel(const float* __restrict__ emb)
{
    int v = blockIdx.x * blockDim.x + threadIdx.x;
    if (v < VV) {
        float s = 0.f;
        #pragma unroll
        for (int c = 0; c < 32; c++) { float e = emb[v*32 + c]; s = fmaf(e, e, s); }
        g_esq[v] = s;
    }
}

// ---------------- init: copy f->frest, zero fhat, stage-0 (pn=1) area pool ----------
// one block per (b,c) map of 256 pixels
__global__ void init_kernel(const float* __restrict__ f, float* __restrict__ out,
                            float* __restrict__ frest, float* __restrict__ rsmall)
{
    __shared__ float red[256];
    int bc = blockIdx.x, t = threadIdx.x;
    float v = f[bc*256 + t];
    frest[bc*256 + t] = v;
    out[bc*256 + t] = 0.f;
    red[t] = v;
    __syncthreads();
    for (int off = 128; off; off >>= 1) {
        if (t < off) red[t] += red[t + off];
        __syncthreads();
    }
    if (t == 0) rsmall[bc] = red[0] / 256.0f;
    if (bc == 0 && t == 0) g_loss = 0.f;
}

// ---------------- NN search: 128-vec x 128-code tile, f32x2 dual-FMA GEMM ----------
__global__ __launch_bounds__(256, 1) void nn_kernel(const float* __restrict__ rest,
                                                    const float* __restrict__ emb,
                                                    int pp, int cpb)
{
    __shared__ __align__(16) float sR[32][128];
    __shared__ __align__(16) float sC[32][128];
    int tid = threadIdx.x;
    int n0 = blockIdx.x << 7;
    int cbase = blockIdx.y * cpb;

    // load + transpose rest tile: sR[c][v]
    for (int j = tid; j < 4096; j += 256) {
        int v = j >> 5, c = j & 31;
        int n = n0 + v;
        int b = n / pp, rem = n - b*pp;
        sR[c][v] = rest[(b*32 + c)*pp + rem];
    }

    float best[8]; int bidx[8];
    #pragma unroll
    for (int i = 0; i < 8; i++) { best[i] = 3.4e38f; bidx[i] = 0; }
    int tx = tid & 15, ty = tid >> 4;
    int nch = cpb >> 7;

    for (int ch = 0; ch < nch; ch++) {
        __syncthreads();
        int cb = cbase + (ch << 7);
        const float* ebase = emb + (size_t)cb * 32;
        for (int j = tid; j < 4096; j += 256) {
            int cl = j >> 5, k = j & 31;
            sC[k][cl] = ebase[cl*32 + k];
        }
        __syncthreads();

        unsigned long long acc[8][4];
        #pragma unroll
        for (int i = 0; i < 8; i++)
            #pragma unroll
            for (int j2 = 0; j2 < 4; j2++) acc[i][j2] = 0ull;

        #pragma unroll 4
        for (int k = 0; k < 32; k++) {
            float4 a0 = *(const float4*)&sR[k][ty*8];
            float4 a1 = *(const float4*)&sR[k][ty*8 + 4];
            ulonglong2 bb0 = *(const ulonglong2*)&sC[k][tx*8];
            ulonglong2 bb1 = *(const ulonglong2*)&sC[k][tx*8 + 4];
            float av[8] = {a0.x,a0.y,a0.z,a0.w,a1.x,a1.y,a1.z,a1.w};
            #pragma unroll
            for (int i = 0; i < 8; i++) {
                unsigned long long ad = dup2(av[i]);
                ffma2(acc[i][0], ad, bb0.x);
                ffma2(acc[i][1], ad, bb0.y);
                ffma2(acc[i][2], ad, bb1.x);
                ffma2(acc[i][3], ad, bb1.y);
            }
        }

        #pragma unroll
        for (int j2 = 0; j2 < 4; j2++) {
            int code = cb + tx*8 + 2*j2;
            float es0 = g_esq[code];
            float es1 = g_esq[code + 1];
            #pragma unroll
            for (int i = 0; i < 8; i++) {
                float lo, hi;
                unpack2(acc[i][j2], lo, hi);
                float s0 = es0 - 2.0f * lo;
                float s1 = es1 - 2.0f * hi;
                if (s0 < best[i]) { best[i] = s0; bidx[i] = code; }
                if (s1 < best[i]) { best[i] = s1; bidx[i] = code + 1; }
            }
        }
    }

    __syncthreads();
    Pair* pr = (Pair*)sC;   // reuse sC (16KB = 128*16 pairs)
    #pragma unroll
    for (int i = 0; i < 8; i++) {
        pr[(ty*8 + i)*16 + tx].v = best[i];
        pr[(ty*8 + i)*16 + tx].i = bidx[i];
    }
    __syncthreads();
    if (tid < 128) {
        Pair p = pr[tid*16];
        #pragma unroll
        for (int t2 = 1; t2 < 16; t2++) {
            Pair q = pr[tid*16 + t2];
            if (q.v < p.v || (q.v == p.v && q.i < p.i)) p = q;
        }
        g_part[(size_t)(n0 + tid)*32 + blockIdx.y] = p;
    }
}

// ---------------- final argmin across splits + write idx + gather emb -> h_small ----
__global__ void reduce_gather_kernel(const float* __restrict__ emb,
                                     float* __restrict__ outIdx,
                                     float* __restrict__ hsm,
                                     int pp, int split)
{
    int lane = threadIdx.x & 31;
    int n = (blockIdx.x << 3) + (threadIdx.x >> 5);
    float v = 3.4e38f; int bi = 0x7fffffff;
    if (lane < split) { Pair p = g_part[(size_t)n*32 + lane]; v = p.v; bi = p.i; }
    #pragma unroll
    for (int off = 16; off; off >>= 1) {
        float ov = __shfl_down_sync(0xffffffffu, v, off);
        int   oi = __shfl_down_sync(0xffffffffu, bi, off);
        if (ov < v || (ov == v && oi < bi)) { v = ov; bi = oi; }
    }
    int idx = __shfl_sync(0xffffffffu, bi, 0);
    if (lane == 0) outIdx[n] = (float)idx;
    int b = n / pp, rem = n - b*pp;
    hsm[(b*32 + lane)*pp + rem] = emb[idx*32 + lane];
}

// ---------------- fused: bicubic up + Phi conv + residual/loss + next-stage pool -----
// one block per image b
__global__ __launch_bounds__(256, 1) void conv_update_kernel(
        const float* __restrict__ hs, const float* __restrict__ W,
        const float* __restrict__ bias, const float* __restrict__ f,
        float* __restrict__ fhat, float* __restrict__ frest,
        float* __restrict__ rsmall,
        int pn, int si, int pnN, int doRest)
{
    extern __shared__ float sm[];
    float* sIn = sm;                    // 32*324 = 10368
    float* sW  = sm + 10368;            // 9216   (reused later as sFr[32][256])
    float* sHs = sm + 10368 + 9216;     // up to 32*169 = 5408
    float* sTw = sHs + 5472;            // 64
    int*   sTi = (int*)(sTw + 64);      // 64
    int b = blockIdx.x, tid = threadIdx.x;
    int pp = pn * pn;

    for (int j = tid; j < 9216; j += 256) sW[j] = W[j];
    if (pn < 16) {
        for (int j = tid; j < 32*pp; j += 256)
            sHs[j] = hs[(size_t)b*32*pp + j];
        if (tid < 64) { sTw[tid] = g_bicW[si*64 + tid]; sTi[tid] = g_bicI[si*64 + tid]; }
    }
    __syncthreads();

    // build sIn (32 x 18 x 18, zero halo); interior = bicubic(hs) or direct copy
    for (int j = tid; j < 32*324; j += 256) {
        int x = j % 18; int t = j / 18; int y = t % 18; int c = t / 18;
        float v = 0.f;
        if (x >= 1 && x <= 16 && y >= 1 && y <= 16) {
            int oy = y - 1, ox = x - 1;
            if (pn == 16) {
                v = hs[((size_t)(b*32 + c) << 8) + oy*16 + ox];
            } else {
                const float* Wy = sTw + oy*4; const int* Iy = sTi + oy*4;
                const float* Wx = sTw + ox*4; const int* Ix = sTi + ox*4;
                const float* base = sHs + c*pp;
                float acc = 0.f;
                #pragma unroll
                for (int txp = 0; txp < 4; txp++) {
                    float col = 0.f;
                    #pragma unroll
                    for (int typ = 0; typ < 4; typ++)
                        col = fmaf(Wy[typ], base[Iy[typ]*pn + Ix[txp]], col);
                    acc = fmaf(Wx[txp], col, acc);
                }
                v = acc;
            }
        }
        sIn[j] = v;
    }
    __syncthreads();

    // 3x3 conv, 32->32: each thread 4 co x 8 px
    int cog = tid >> 5;
    int pxg = tid & 31;
    int p0 = pxg << 3;
    int y = p0 >> 4, x0 = p0 & 15;

    float acc[4][8];
    #pragma unroll
    for (int q = 0; q < 4; q++)
        #pragma unroll
        for (int m = 0; m < 8; m++) acc[q][m] = 0.f;

    for (int ci = 0; ci < 32; ci++) {
        const float* inC = sIn + ci*324;
        const float* wC  = sW + (cog*4)*288 + ci*9;
        #pragma unroll
        for (int dy = 0; dy < 3; dy++) {
            float row[10];
            const float* r = inC + (y + dy)*18 + x0;
            #pragma unroll
            for (int j = 0; j < 10; j++) row[j] = r[j];
            #pragma unroll
            for (int dx = 0; dx < 3; dx++) {
                float w0 = wC[0*288 + dy*3 + dx];
                float w1 = wC[1*288 + dy*3 + dx];
                float w2 = wC[2*288 + dy*3 + dx];
                float w3 = wC[3*288 + dy*3 + dx];
                #pragma unroll
                for (int m = 0; m < 8; m++) {
                    float iv = row[dx + m];
                    acc[0][m] = fmaf(w0, iv, acc[0][m]);
                    acc[1][m] = fmaf(w1, iv, acc[1][m]);
                    acc[2][m] = fmaf(w2, iv, acc[2][m]);
                    acc[3][m] = fmaf(w3, iv, acc[3][m]);
                }
            }
        }
    }
    __syncthreads();                    // all sW reads done; safe to reuse as sFr

    float* sFr = sW;                    // [32][256] new residual for pooling
    float lsum = 0.f;
    #pragma unroll
    for (int q = 0; q < 4; q++) {
        int co = cog*4 + q;
        float bv = bias[co];
        #pragma unroll
        for (int m = 0; m < 8; m++) {
            int px = x0 + m;
            int li = co*256 + y*16 + px;
            int gi = ((b*32 + co)*16 + y)*16 + px;
            float hv = sIn[co*324 + (y + 1)*18 + (px + 1)];
            float h = hv*0.5f + (acc[q][m] + bv)*0.5f;   // r = 0.5
            float fh = fhat[gi] + h;
            fhat[gi] = fh;
            if (doRest) {
                float fr = frest[gi] - h;
                frest[gi] = fr;
                sFr[li] = fr;
            }
            float d = fh - f[gi];
            lsum += d*d;
        }
    }
    #pragma unroll
    for (int off = 16; off; off >>= 1) lsum += __shfl_down_sync(0xffffffffu, lsum, off);
    if ((tid & 31) == 0) atomicAdd(&g_loss, lsum);

    // area-pool new residual -> next stage's rest
    if (pnN > 0) {
        __syncthreads();
        int ppN = pnN * pnN;
        for (int j = tid; j < 32*ppN; j += 256) {
            int ox = j % pnN; int t = j / pnN;
            int oy = t % pnN; int c = t / pnN;
            int sy0 = (oy*16)/pnN,      sy1 = ((oy+1)*16 + pnN - 1)/pnN;
            int sx0 = (ox*16)/pnN,      sx1 = ((ox+1)*16 + pnN - 1)/pnN;
            const float* base = sFr + c*256;
            float s = 0.f;
            for (int yy = sy0; yy < sy1; yy++)
                for (int xx = sx0; xx < sx1; xx++)
                    s += base[yy*16 + xx];
            rsmall[((size_t)(b*32 + c))*ppN + oy*pnN + ox] = s / (float)((sy1-sy0)*(sx1-sx0));
        }
    }
}

__global__ void fin_kernel(float* __restrict__ out)
{
    if (threadIdx.x == 0)
        out[NPIX] = g_loss * 1.25f / 10.0f / 1048576.0f;
}

// =====================================================================================
extern "C" void kernel_launch(void* const* d_in, const int* in_sizes, int n_in,
                              void* d_out, int out_size)
{
    const float* f    = (const float*)d_in[0];
    const float* emb  = (const float*)d_in[1];
    const float* phiW = (const float*)d_in[2];
    const float* phib = (const float*)d_in[3];
    float* out = (float*)d_out;

    float *frest, *rsmall, *hsm;
    cudaGetSymbolAddress((void**)&frest,  g_frest);
    cudaGetSymbolAddress((void**)&rsmall, g_rsmall);
    cudaGetSymbolAddress((void**)&hsm,    g_hsmall);

    static const int pns[10] = {1,2,3,4,5,6,8,10,13,16};

    // phi index map: replicate np.linspace + argmin(|ticks - si/9|) in exact doubles
    int kmap[10];
    {
        double start = 1.0/(3.0*4.0);
        double stop  = 1.0 - 1.0/(3.0*4.0);
        double step  = (stop - start)/3.0;
        double ticks[4];
        for (int i2 = 0; i2 < 4; i2++) ticks[i2] = (double)i2*step + start;
        ticks[3] = stop;
        for (int si = 0; si < 10; si++) {
            double s = (double)si / 9.0;
            int bk = 0; double bvv = fabs(ticks[0] - s);
            for (int i2 = 1; i2 < 4; i2++) {
                double vv = fabs(ticks[i2] - s);
                if (vv < bvv) { bvv = vv; bk = i2; }
            }
            kmap[si] = bk;
        }
    }

    int convSmem = (10368 + 9216 + 5472 + 64) * 4 + 64 * 4;
    cudaFuncSetAttribute(conv_update_kernel,
                         cudaFuncAttributeMaxDynamicSharedMemorySize, convSmem);

    taps_kernel<<<1, 160>>>();
    esq_kernel<<<16, 256>>>(emb);
    init_kernel<<<4096, 256>>>(f, out, frest, rsmall);

    float* idxbase = out + NPIX + 1;
    int idxoff = 0;
    for (int si = 0; si < 10; si++) {
        int pn = pns[si], pp = pn*pn;
        int N = 128*pp;
        const float* rest = (si == 9) ? frest : rsmall;

        int nvb = N/128;
        int split = 1;
        while (split < 32 && nvb*split < 256) split <<= 1;   // target >=256 blocks
        dim3 g(nvb, split);
        nn_kernel<<<g, 256>>>(rest, emb, pp, VV/split);
        reduce_gather_kernel<<<N/8, 256>>>(emb, idxbase + idxoff, hsm, pp, split);

        int pnN    = (si <= 7) ? pns[si+1] : 0;   // stage 8 -> stage 9 uses frest directly
        int doRest = (si <= 8) ? 1 : 0;
        conv_update_kernel<<<128, 256, convSmem>>>(hsm,
                phiW + kmap[si]*32*32*9, phib + kmap[si]*32, f, out, frest, rsmall,
                pn, si, pnN, doRest);
        idxoff += N;
    }
    fin_kernel<<<1, 32>>>(out);
}

// round 4
// speedup vs baseline: 1.5550x; 1.5431x over previous
#include <cuda_runtime.h>
#include <math.h>
#include <stdint.h>

#define NPIX (128*32*16*16)   // 1048576
#define VV 4096

struct Pair { float v; int i; };

// ---------------- static device scratch ----------------
__device__ float g_frest[NPIX];
__device__ float g_rsmall[128*32*169];
__device__ float g_hsmall[NPIX];
__device__ float g_esq[VV];
__device__ float g_ehi[VV*32];
__device__ float g_elo[VV*32];
__device__ float g_bicW[9*16*4];
__device__ int   g_bicI[9*16*4];
__device__ Pair  g_part[32768*32];
__device__ float g_loss;

// ---------------- helpers ----------------
__device__ __forceinline__ uint32_t smem_u32(const void* p) {
    uint32_t a;
    asm("{ .reg .u64 t; cvta.to.shared.u64 t, %1; cvt.u32.u64 %0, t; }" : "=r"(a) : "l"(p));
    return a;
}
__device__ __forceinline__ float tf32_rna(float x) {
    uint32_t r; asm("cvt.rna.tf32.f32 %0, %1;" : "=r"(r) : "f"(x));
    return __uint_as_float(r);
}
__device__ __forceinline__ void mma_tf32(float c[4], const uint32_t a[4], const uint32_t b[2])
{
    asm volatile("mma.sync.aligned.m16n8k8.row.col.f32.tf32.tf32.f32 "
        "{%0,%1,%2,%3},{%4,%5,%6,%7},{%8,%9},{%0,%1,%2,%3};"
        : "+f"(c[0]), "+f"(c[1]), "+f"(c[2]), "+f"(c[3])
        : "r"(a[0]), "r"(a[1]), "r"(a[2]), "r"(a[3]), "r"(b[0]), "r"(b[1]));
}
#define CPA16(dst, src) \
    asm volatile("cp.async.cg.shared.global [%0], [%1], 16;" :: "r"(dst), "l"(src) : "memory")
#define CPA_COMMIT() asm volatile("cp.async.commit_group;" ::: "memory")
#define CPA_WAIT1()  asm volatile("cp.async.wait_group 1;" ::: "memory")
#define CPA_WAIT0()  asm volatile("cp.async.wait_group 0;" ::: "memory")

// ---------------- bicubic tap tables ----------------
__global__ void taps_kernel()
{
    int t = blockIdx.x * blockDim.x + threadIdx.x;
    if (t >= 144) return;
    int si = t >> 4, o = t & 15;
    const int pns[10] = {1,2,3,4,5,6,8,10,13,16};
    int in_s = pns[si];
    double src = (o + 0.5) * (double)in_s / 16.0 - 0.5;
    double fl = floor(src);
    const double a = -0.75;
    for (int tt = 0; tt < 4; tt++) {
        double x = fabs(src - (fl + (double)(tt - 1)));
        double w;
        if (x <= 1.0)      w = (a + 2.0)*x*x*x - (a + 3.0)*x*x + 1.0;
        else if (x < 2.0)  w = a*x*x*x - 5.0*a*x*x + 8.0*a*x - 4.0*a;
        else               w = 0.0;
        int idx = (int)fl + (tt - 1);
        if (idx < 0) idx = 0;
        if (idx > in_s - 1) idx = in_s - 1;
        g_bicW[(si*16 + o)*4 + tt] = (float)w;
        g_bicI[(si*16 + o)*4 + tt] = idx;
    }
}

// ---------------- e_sq + tf32 hi/lo split of emb ----------------
__global__ void esq_kernel(const float* __restrict__ emb)
{
    int v = blockIdx.x * blockDim.x + threadIdx.x;
    if (v < VV) {
        float s = 0.f;
        #pragma unroll
        for (int c = 0; c < 32; c++) { float e = emb[v*32 + c]; s = fmaf(e, e, s); }
        g_esq[v] = s;
    }
}
__global__ void prep_kernel(const float* __restrict__ emb)
{
    int i = blockIdx.x * blockDim.x + threadIdx.x;
    if (i < VV*32) {
        float x = emb[i];
        float h = tf32_rna(x);
        g_ehi[i] = h;
        g_elo[i] = tf32_rna(x - h);
    }
}

// ---------------- init ----------------
__global__ void init_kernel(const float* __restrict__ f, float* __restrict__ out,
                            float* __restrict__ frest, float* __restrict__ rsmall)
{
    __shared__ float red[256];
    int bc = blockIdx.x, t = threadIdx.x;
    float v = f[bc*256 + t];
    frest[bc*256 + t] = v;
    out[bc*256 + t] = 0.f;
    red[t] = v;
    __syncthreads();
    for (int off = 128; off; off >>= 1) {
        if (t < off) red[t] += red[t + off];
        __syncthreads();
    }
    if (t == 0) rsmall[bc] = red[0] / 256.0f;
    if (bc == 0 && t == 0) g_loss = 0.f;
}

// ---------------- NN search: mma.sync tf32 3x-split GEMM + argmin ----------------
// smem float layout:
//   svH 0 (64x36)  svL 2304  esq 4608 (2x128)  codes 4864 (2 bufs x (hi 128x36 + lo 128x36))
//   redV 23296 (256)  redI 23552 (256)   total 23808 floats = 95232 B
#define F_SVH 0
#define F_SVL 2304
#define F_ESQ 4608
#define F_SC  4864
#define F_RDV 23296
#define F_RDI 23552
#define NN_SMEM_B (23808*4)

__global__ __launch_bounds__(256, 2) void nn_mma_kernel(const float* __restrict__ rest,
                                                        int pp, int cpb)
{
    extern __shared__ __align__(16) float sm[];
    uint32_t sb = smem_u32(sm);
    int tid = threadIdx.x;
    int lane = tid & 31, warp = tid >> 5;
    int g = lane >> 2, t = lane & 3;
    int cg = warp & 3, vg = warp >> 2;
    int n0 = blockIdx.x << 6;                 // 64 vectors per block
    int cb0 = blockIdx.y * cpb;
    int nb = cpb >> 7;                        // chunks of 128 codes

    // stage the block's 64 vectors (hi/lo split) into smem
    for (int j = tid; j < 2048; j += 256) {
        int v = j >> 5, c = j & 31;
        int n = n0 + v; int b = n / pp, rem = n - b*pp;
        float x = rest[(b*32 + c)*pp + rem];
        float h = tf32_rna(x);
        sm[F_SVH + v*36 + c] = h;
        sm[F_SVL + v*36 + c] = tf32_rna(x - h);
    }

    // prologue: async-load chunk 0
    {
        int buf = 0, cb = cb0;
        #pragma unroll
        for (int i = 0; i < 8; i++) {
            int gi = i*256 + tid;
            int half = gi >> 10, r = (gi >> 3) & 127, q = gi & 7;
            const float* src = (half ? g_elo : g_ehi) + (size_t)(cb + r)*32 + q*4;
            uint32_t dst = sb + (uint32_t)(F_SC + buf*9216 + half*4608 + r*36 + q*4)*4;
            CPA16(dst, src);
        }
        if (tid < 32) CPA16(sb + (uint32_t)(F_ESQ + buf*128 + tid*4)*4, g_esq + cb + tid*4);
        CPA_COMMIT();
    }

    float best[8]; int bidx[8];
    #pragma unroll
    for (int i = 0; i < 8; i++) { best[i] = 3.4e38f; bidx[i] = 0; }

    int rowb = cg*32;
    int vecb = vg*32;

    for (int j = 0; j < nb; j++) {
        int buf = j & 1;
        if (j + 1 < nb) {                      // prefetch next chunk
            int b2 = buf ^ 1, cb = cb0 + (j + 1)*128;
            #pragma unroll
            for (int i = 0; i < 8; i++) {
                int gi = i*256 + tid;
                int half = gi >> 10, r = (gi >> 3) & 127, q = gi & 7;
                const float* src = (half ? g_elo : g_ehi) + (size_t)(cb + r)*32 + q*4;
                uint32_t dst = sb + (uint32_t)(F_SC + b2*9216 + half*4608 + r*36 + q*4)*4;
                CPA16(dst, src);
            }
            if (tid < 32) CPA16(sb + (uint32_t)(F_ESQ + b2*128 + tid*4)*4, g_esq + cb + tid*4);
            CPA_COMMIT();
            CPA_WAIT1();
        } else {
            CPA_WAIT0();
        }
        __syncthreads();

        const float* cH = sm + F_SC + buf*9216;
        const float* cL = cH + 4608;
        const float* vH = sm + F_SVH;
        const float* vL = sm + F_SVL;
        const float* eq = sm + F_ESQ + buf*128;

        float C[2][4][4];
        #pragma unroll
        for (int mt = 0; mt < 2; mt++)
            #pragma unroll
            for (int nt = 0; nt < 4; nt++)
                #pragma unroll
                for (int q = 0; q < 4; q++) C[mt][nt][q] = 0.f;

        #pragma unroll
        for (int ks = 0; ks < 4; ks++) {
            int k0 = ks*8 + t;
            uint32_t Ah[2][4], Al[2][4], Bh[4][2], Bl[4][2];
            #pragma unroll
            for (int mt = 0; mt < 2; mt++) {
                int r0 = (rowb + mt*16 + g)*36;
                Ah[mt][0] = __float_as_uint(cH[r0 + k0]);
                Ah[mt][1] = __float_as_uint(cH[r0 + 288 + k0]);       // +8 rows
                Ah[mt][2] = __float_as_uint(cH[r0 + k0 + 4]);
                Ah[mt][3] = __float_as_uint(cH[r0 + 288 + k0 + 4]);
                Al[mt][0] = __float_as_uint(cL[r0 + k0]);
                Al[mt][1] = __float_as_uint(cL[r0 + 288 + k0]);
                Al[mt][2] = __float_as_uint(cL[r0 + k0 + 4]);
                Al[mt][3] = __float_as_uint(cL[r0 + 288 + k0 + 4]);
            }
            #pragma unroll
            for (int nt = 0; nt < 4; nt++) {
                int n = (vecb + nt*8 + g)*36;
                Bh[nt][0] = __float_as_uint(vH[n + k0]);
                Bh[nt][1] = __float_as_uint(vH[n + k0 + 4]);
                Bl[nt][0] = __float_as_uint(vL[n + k0]);
                Bl[nt][1] = __float_as_uint(vL[n + k0 + 4]);
            }
            #pragma unroll
            for (int mt = 0; mt < 2; mt++)
                #pragma unroll
                for (int nt = 0; nt < 4; nt++) {
                    mma_tf32(C[mt][nt], Ah[mt], Bh[nt]);
                    mma_tf32(C[mt][nt], Ah[mt], Bl[nt]);
                    mma_tf32(C[mt][nt], Al[mt], Bh[nt]);
                }
        }

        // scores + running argmin (ascending code order within thread -> strict <)
        #pragma unroll
        for (int mt = 0; mt < 2; mt++)
            #pragma unroll
            for (int r = 0; r < 2; r++) {
                int locc = rowb + mt*16 + r*8 + g;
                int code = cb0 + j*128 + locc;
                float es = eq[locc];
                #pragma unroll
                for (int nt = 0; nt < 4; nt++)
                    #pragma unroll
                    for (int q = 0; q < 2; q++) {
                        float s = fmaf(-2.0f, C[mt][nt][r*2 + q], es);
                        int sl = nt*2 + q;
                        if (s < best[sl]) { best[sl] = s; bidx[sl] = code; }
                    }
            }
        __syncthreads();
    }

    // reduce over g lanes (same t) via xor shuffles, with index tie-break
    #pragma unroll
    for (int sl = 0; sl < 8; sl++) {
        #pragma unroll
        for (int off = 4; off <= 16; off <<= 1) {
            float ov = __shfl_xor_sync(0xffffffffu, best[sl], off);
            int   oi = __shfl_xor_sync(0xffffffffu, bidx[sl], off);
            if (ov < best[sl] || (ov == best[sl] && oi < bidx[sl])) {
                best[sl] = ov; bidx[sl] = oi;
            }
        }
    }
    // lanes 0..3 (g==0) publish per-vector candidates for this code-group
    if (g == 0) {
        #pragma unroll
        for (int nt = 0; nt < 4; nt++)
            #pragma unroll
            for (int q = 0; q < 2; q++) {
                int vloc = vecb + nt*8 + 2*t + q;
                sm[F_RDV + vloc*4 + cg] = best[nt*2 + q];
                ((int*)sm)[F_RDI + vloc*4 + cg] = bidx[nt*2 + q];
            }
    }
    __syncthreads();
    if (tid < 64) {
        float v = sm[F_RDV + tid*4]; int bi = ((int*)sm)[F_RDI + tid*4];
        #pragma unroll
        for (int c2 = 1; c2 < 4; c2++) {
            float ov = sm[F_RDV + tid*4 + c2];
            int   oi = ((int*)sm)[F_RDI + tid*4 + c2];
            if (ov < v || (ov == v && oi < bi)) { v = ov; bi = oi; }
        }
        g_part[(size_t)(n0 + tid)*32 + blockIdx.y] = Pair{v, bi};
    }
}

// ---------------- final argmin across splits + write idx + gather emb ----------------
__global__ void reduce_gather_kernel(const float* __restrict__ emb,
                                     float* __restrict__ outIdx,
                                     float* __restrict__ hsm,
                                     int pp, int split)
{
    int lane = threadIdx.x & 31;
    int n = (blockIdx.x << 3) + (threadIdx.x >> 5);
    float v = 3.4e38f; int bi = 0x7fffffff;
    if (lane < split) { Pair p = g_part[(size_t)n*32 + lane]; v = p.v; bi = p.i; }
    #pragma unroll
    for (int off = 16; off; off >>= 1) {
        float ov = __shfl_down_sync(0xffffffffu, v, off);
        int   oi = __shfl_down_sync(0xffffffffu, bi, off);
        if (ov < v || (ov == v && oi < bi)) { v = ov; bi = oi; }
    }
    int idx = __shfl_sync(0xffffffffu, bi, 0);
    if (lane == 0) outIdx[n] = (float)idx;
    int b = n / pp, rem = n - b*pp;
    hsm[(b*32 + lane)*pp + rem] = emb[idx*32 + lane];
}

// ---------------- fused: bicubic up + Phi conv + residual/loss + next pool ----------
__global__ __launch_bounds__(256, 1) void conv_update_kernel(
        const float* __restrict__ hs, const float* __restrict__ W,
        const float* __restrict__ bias, const float* __restrict__ f,
        float* __restrict__ fhat, float* __restrict__ frest,
        float* __restrict__ rsmall,
        int pn, int si, int pnN, int doRest)
{
    extern __shared__ float smf[];
    float* sIn = smf;
    float* sW  = smf + 10368;
    float* sHs = smf + 10368 + 9216;
    float* sTw = sHs + 5472;
    int*   sTi = (int*)(sTw + 64);
    int b = blockIdx.x, tid = threadIdx.x;
    int pp = pn * pn;

    for (int j = tid; j < 9216; j += 256) sW[j] = W[j];
    if (pn < 16) {
        for (int j = tid; j < 32*pp; j += 256)
            sHs[j] = hs[(size_t)b*32*pp + j];
        if (tid < 64) { sTw[tid] = g_bicW[si*64 + tid]; sTi[tid] = g_bicI[si*64 + tid]; }
    }
    __syncthreads();

    for (int j = tid; j < 32*324; j += 256) {
        int x = j % 18; int t = j / 18; int y = t % 18; int c = t / 18;
        float v = 0.f;
        if (x >= 1 && x <= 16 && y >= 1 && y <= 16) {
            int oy = y - 1, ox = x - 1;
            if (pn == 16) {
                v = hs[((size_t)(b*32 + c) << 8) + oy*16 + ox];
            } else {
                const float* Wy = sTw + oy*4; const int* Iy = sTi + oy*4;
                const float* Wx = sTw + ox*4; const int* Ix = sTi + ox*4;
                const float* base = sHs + c*pp;
                float acc = 0.f;
                #pragma unroll
                for (int txp = 0; txp < 4; txp++) {
                    float col = 0.f;
                    #pragma unroll
                    for (int typ = 0; typ < 4; typ++)
                        col = fmaf(Wy[typ], base[Iy[typ]*pn + Ix[txp]], col);
                    acc = fmaf(Wx[txp], col, acc);
                }
                v = acc;
            }
        }
        sIn[j] = v;
    }
    __syncthreads();

    int cog = tid >> 5;
    int pxg = tid & 31;
    int p0 = pxg << 3;
    int y = p0 >> 4, x0 = p0 & 15;

    float acc[4][8];
    #pragma unroll
    for (int q = 0; q < 4; q++)
        #pragma unroll
        for (int m = 0; m < 8; m++) acc[q][m] = 0.f;

    for (int ci = 0; ci < 32; ci++) {
        const float* inC = sIn + ci*324;
        const float* wC  = sW + (cog*4)*288 + ci*9;
        #pragma unroll
        for (int dy = 0; dy < 3; dy++) {
            float row[10];
            const float* r = inC + (y + dy)*18 + x0;
            #pragma unroll
            for (int j = 0; j < 10; j++) row[j] = r[j];
            #pragma unroll
            for (int dx = 0; dx < 3; dx++) {
                float w0 = wC[0*288 + dy*3 + dx];
                float w1 = wC[1*288 + dy*3 + dx];
                float w2 = wC[2*288 + dy*3 + dx];
                float w3 = wC[3*288 + dy*3 + dx];
                #pragma unroll
                for (int m = 0; m < 8; m++) {
                    float iv = row[dx + m];
                    acc[0][m] = fmaf(w0, iv, acc[0][m]);
                    acc[1][m] = fmaf(w1, iv, acc[1][m]);
                    acc[2][m] = fmaf(w2, iv, acc[2][m]);
                    acc[3][m] = fmaf(w3, iv, acc[3][m]);
                }
            }
        }
    }
    __syncthreads();

    float* sFr = sW;
    float lsum = 0.f;
    #pragma unroll
    for (int q = 0; q < 4; q++) {
        int co = cog*4 + q;
        float bv = bias[co];
        #pragma unroll
        for (int m = 0; m < 8; m++) {
            int px = x0 + m;
            int li = co*256 + y*16 + px;
            int gi = ((b*32 + co)*16 + y)*16 + px;
            float hv = sIn[co*324 + (y + 1)*18 + (px + 1)];
            float h = hv*0.5f + (acc[q][m] + bv)*0.5f;
            float fh = fhat[gi] + h;
            fhat[gi] = fh;
            if (doRest) {
                float fr = frest[gi] - h;
                frest[gi] = fr;
                sFr[li] = fr;
            }
            float d = fh - f[gi];
            lsum += d*d;
        }
    }
    #pragma unroll
    for (int off = 16; off; off >>= 1) lsum += __shfl_down_sync(0xffffffffu, lsum, off);
    if ((tid & 31) == 0) atomicAdd(&g_loss, lsum);

    if (pnN > 0) {
        __syncthreads();
        int ppN = pnN * pnN;
        for (int j = tid; j < 32*ppN; j += 256) {
            int ox = j % pnN; int t = j / pnN;
            int oy = t % pnN; int c = t / pnN;
            int sy0 = (oy*16)/pnN,      sy1 = ((oy+1)*16 + pnN - 1)/pnN;
            int sx0 = (ox*16)/pnN,      sx1 = ((ox+1)*16 + pnN - 1)/pnN;
            const float* base = sFr + c*256;
            float s = 0.f;
            for (int yy = sy0; yy < sy1; yy++)
                for (int xx = sx0; xx < sx1; xx++)
                    s += base[yy*16 + xx];
            rsmall[((size_t)(b*32 + c))*ppN + oy*pnN + ox] = s / (float)((sy1-sy0)*(sx1-sx0));
        }
    }
}

__global__ void fin_kernel(float* __restrict__ out)
{
    if (threadIdx.x == 0)
        out[NPIX] = g_loss * 1.25f / 10.0f / 1048576.0f;
}

// =====================================================================================
extern "C" void kernel_launch(void* const* d_in, const int* in_sizes, int n_in,
                              void* d_out, int out_size)
{
    const float* f    = (const float*)d_in[0];
    const float* emb  = (const float*)d_in[1];
    const float* phiW = (const float*)d_in[2];
    const float* phib = (const float*)d_in[3];
    float* out = (float*)d_out;

    float *frest, *rsmall, *hsm;
    cudaGetSymbolAddress((void**)&frest,  g_frest);
    cudaGetSymbolAddress((void**)&rsmall, g_rsmall);
    cudaGetSymbolAddress((void**)&hsm,    g_hsmall);

    static const int pns[10]    = {1,2,3,4,5,6,8,10,13,16};
    static const int splits[10] = {32,16,8,8,4,2,2,1,1,1};

    int kmap[10];
    {
        double start = 1.0/(3.0*4.0);
        double stop  = 1.0 - 1.0/(3.0*4.0);
        double step  = (stop - start)/3.0;
        double ticks[4];
        for (int i2 = 0; i2 < 4; i2++) ticks[i2] = (double)i2*step + start;
        ticks[3] = stop;
        for (int si = 0; si < 10; si++) {
            double s = (double)si / 9.0;
            int bk = 0; double bvv = fabs(ticks[0] - s);
            for (int i2 = 1; i2 < 4; i2++) {
                double vv = fabs(ticks[i2] - s);
                if (vv < bvv) { bvv = vv; bk = i2; }
            }
            kmap[si] = bk;
        }
    }

    int convSmem = (10368 + 9216 + 5472 + 64) * 4 + 64 * 4;
    cudaFuncSetAttribute(conv_update_kernel,
                         cudaFuncAttributeMaxDynamicSharedMemorySize, convSmem);
    cudaFuncSetAttribute(nn_mma_kernel,
                         cudaFuncAttributeMaxDynamicSharedMemorySize, NN_SMEM_B);

    taps_kernel<<<1, 160>>>();
    esq_kernel<<<16, 256>>>(emb);
    prep_kernel<<<512, 256>>>(emb);
    init_kernel<<<4096, 256>>>(f, out, frest, rsmall);

    float* idxbase = out + NPIX + 1;
    int idxoff = 0;
    for (int si = 0; si < 10; si++) {
        int pn = pns[si], pp = pn*pn;
        int N = 128*pp;
        const float* rest = (si == 9) ? frest : rsmall;

        int split = splits[si];
        dim3 g(N/64, split);
        nn_mma_kernel<<<g, 256, NN_SMEM_B>>>(rest, pp, VV/split);
        reduce_gather_kernel<<<N/8, 256>>>(emb, idxbase + idxoff, hsm, pp, split);

        int pnN    = (si <= 7) ? pns[si+1] : 0;
        int doRest = (si <= 8) ? 1 : 0;
        conv_update_kernel<<<128, 256, convSmem>>>(hsm,
                phiW + kmap[si]*32*32*9, phib + kmap[si]*32, f, out, frest, rsmall,
                pn, si, pnN, doRest);
        idxoff += N;
    }
    fin_kernel<<<1, 32>>>(out);
}

// round 5
// speedup vs baseline: 1.7106x; 1.1001x over previous
#include <cuda_runtime.h>
#include <math.h>
#include <stdint.h>

#define NPIX (128*32*16*16)   // 1048576
#define VV 4096

struct Pair { float v; int i; };

// ---------------- static device scratch ----------------
__device__ float g_frest[NPIX];
__device__ float g_rsmall[128*32*169];
__device__ float g_hsmall[NPIX];
__device__ float g_eafrag[32*8320];     // 32 chunks x (2048 A-frag f4 + 32 esq f4)
__device__ float g_bicW[9*16*4];
__device__ int   g_bicI[9*16*4];
__device__ Pair  g_part[32768*32];
__device__ float g_loss;

// ---------------- helpers ----------------
__device__ __forceinline__ uint32_t smem_u32(const void* p) {
    uint32_t a;
    asm("{ .reg .u64 t; cvta.to.shared.u64 t, %1; cvt.u32.u64 %0, t; }" : "=r"(a) : "l"(p));
    return a;
}
__device__ __forceinline__ float tf32_rna(float x) {
    uint32_t r; asm("cvt.rna.tf32.f32 %0, %1;" : "=r"(r) : "f"(x));
    return __uint_as_float(r);
}
__device__ __forceinline__ void mma_tf32(float c[4], const uint32_t* a, uint32_t b0, uint32_t b1)
{
    asm volatile("mma.sync.aligned.m16n8k8.row.col.f32.tf32.tf32.f32 "
        "{%0,%1,%2,%3},{%4,%5,%6,%7},{%8,%9},{%0,%1,%2,%3};"
        : "+f"(c[0]), "+f"(c[1]), "+f"(c[2]), "+f"(c[3])
        : "r"(a[0]), "r"(a[1]), "r"(a[2]), "r"(a[3]), "r"(b0), "r"(b1));
}
#define CPA16(dst, src) \
    asm volatile("cp.async.cg.shared.global [%0], [%1], 16;" :: "r"(dst), "l"(src) : "memory")
#define CPA_COMMIT() asm volatile("cp.async.commit_group;" ::: "memory")
#define CPA_WAIT0()  asm volatile("cp.async.wait_group 0;" ::: "memory")

// ---------------- bicubic tap tables ----------------
__global__ void taps_kernel()
{
    int t = blockIdx.x * blockDim.x + threadIdx.x;
    if (t >= 144) return;
    int si = t >> 4, o = t & 15;
    const int pns[10] = {1,2,3,4,5,6,8,10,13,16};
    int in_s = pns[si];
    double src = (o + 0.5) * (double)in_s / 16.0 - 0.5;
    double fl = floor(src);
    const double a = -0.75;
    for (int tt = 0; tt < 4; tt++) {
        double x = fabs(src - (fl + (double)(tt - 1)));
        double w;
        if (x <= 1.0)      w = (a + 2.0)*x*x*x - (a + 3.0)*x*x + 1.0;
        else if (x < 2.0)  w = a*x*x*x - 5.0*a*x*x + 8.0*a*x - 4.0*a;
        else               w = 0.0;
        int idx = (int)fl + (tt - 1);
        if (idx < 0) idx = 0;
        if (idx > in_s - 1) idx = in_s - 1;
        g_bicW[(si*16 + o)*4 + tt] = (float)w;
        g_bicI[(si*16 + o)*4 + tt] = idx;
    }
}

// ---------------- prep: emb -> fragment-ordered hi/lo + esq frags ----------------
__global__ void prep_kernel(const float* __restrict__ emb, float* __restrict__ eaf)
{
    int e = blockIdx.x * blockDim.x + threadIdx.x;
    if (e >= 32*2080) return;
    int chunk = e / 2080;
    int i = e - chunk*2080;
    float4* dst = (float4*)(eaf + (size_t)chunk*8320);
    if (i < 2048) {
        int lane = i & 31;
        int r1 = i >> 5;
        int half = r1 & 1, mt = (r1 >> 1) & 1, ks = (r1 >> 2) & 3, cg = r1 >> 4;
        int g = lane >> 2, t = lane & 3;
        int code0 = chunk*128 + cg*32 + mt*16 + g;
        int k0 = ks*8 + t;
        float x0 = emb[code0*32 + k0];
        float x1 = emb[(code0+8)*32 + k0];
        float x2 = emb[code0*32 + k0 + 4];
        float x3 = emb[(code0+8)*32 + k0 + 4];
        float4 v;
        if (half == 0) {
            v.x = tf32_rna(x0); v.y = tf32_rna(x1);
            v.z = tf32_rna(x2); v.w = tf32_rna(x3);
        } else {
            v.x = tf32_rna(x0 - tf32_rna(x0)); v.y = tf32_rna(x1 - tf32_rna(x1));
            v.z = tf32_rna(x2 - tf32_rna(x2)); v.w = tf32_rna(x3 - tf32_rna(x3));
        }
        dst[i] = v;
    } else {
        int ii = i - 2048;          // 0..31: esq frag
        int cg = ii >> 3, g = ii & 7;
        float4 v; float* vv = &v.x;
        #pragma unroll
        for (int mt = 0; mt < 2; mt++)
            #pragma unroll
            for (int r = 0; r < 2; r++) {
                int code = chunk*128 + cg*32 + mt*16 + r*8 + g;
                float s = 0.f;
                #pragma unroll
                for (int c = 0; c < 32; c++) { float ee = emb[code*32 + c]; s = fmaf(ee, ee, s); }
                vv[mt*2 + r] = s;
            }
        dst[i] = v;
    }
}

// ---------------- init ----------------
__global__ void init_kernel(const float* __restrict__ f, float* __restrict__ out,
                            float* __restrict__ frest, float* __restrict__ rsmall)
{
    __shared__ float red[256];
    int bc = blockIdx.x, t = threadIdx.x;
    float v = f[bc*256 + t];
    frest[bc*256 + t] = v;
    out[bc*256 + t] = 0.f;
    red[t] = v;
    __syncthreads();
    for (int off = 128; off; off >>= 1) {
        if (t < off) red[t] += red[t + off];
        __syncthreads();
    }
    if (t == 0) rsmall[bc] = red[0] / 256.0f;
    if (bc == 0 && t == 0) g_loss = 0.f;
}

// ---------------- NN search: frag-ordered tf32 mma + argmin ----------------
#define SVF 0
#define BUFF 4096
#define RDVF 20736
#define RDIF 20992
#define SIDXF 21248
#define NN_SMEM_B (21312*4)

__global__ __launch_bounds__(256, 2) void nn_mma_kernel(
        const float* __restrict__ rest, const float* __restrict__ eaf,
        const float* __restrict__ emb,
        float* __restrict__ outIdx, float* __restrict__ hsm,
        int pp, int cpb, int split)
{
    extern __shared__ __align__(16) float sm[];
    uint32_t sb = smem_u32(sm);
    int tid = threadIdx.x;
    int lane = tid & 31, warp = tid >> 5;
    int g = lane >> 2, t = lane & 3;
    int cg = warp & 3, vg = warp >> 2;
    int n0 = blockIdx.x << 6;
    int cb0 = blockIdx.y * cpb;
    int ch0 = cb0 >> 7;
    int nb = cpb >> 7;

    // prologue: cp.async chunk0 -> buf0
    {
        const float4* src = (const float4*)(eaf + (size_t)ch0*8320);
        uint32_t dst = sb + BUFF*4;
        #pragma unroll
        for (int i = 0; i < 8; i++) CPA16(dst + (uint32_t)(tid + i*256)*16, src + tid + i*256);
        if (tid < 32) CPA16(dst + (uint32_t)(2048 + tid)*16, src + 2048 + tid);
        CPA_COMMIT();
    }
    // build vector (B) frags: [ks][ntg][lane] float4 = (b0h,b1h,b0l,b1l)
    #pragma unroll
    for (int it = 0; it < 4; it++) {
        int e = tid + it*256;
        int ln = e & 31, ntg = (e >> 5) & 7, ks = e >> 8;
        int col = ntg*8 + (ln >> 2), tt = ln & 3;
        int k0 = ks*8 + tt;
        int n = n0 + col; int b = n / pp, rem = n - b*pp;
        float xa = rest[(b*32 + k0)*pp + rem];
        float xb = rest[(b*32 + k0 + 4)*pp + rem];
        float ha = tf32_rna(xa), hb = tf32_rna(xb);
        float4 v; v.x = ha; v.y = hb; v.z = tf32_rna(xa - ha); v.w = tf32_rna(xb - hb);
        ((float4*)sm)[e] = v;
    }

    float best[8]; int bidx[8];
    #pragma unroll
    for (int i = 0; i < 8; i++) { best[i] = 3.4e38f; bidx[i] = 0; }

    const float4* sV = (const float4*)sm;

    for (int j = 0; j < nb; j++) {
        int buf = j & 1;
        CPA_WAIT0();
        __syncthreads();
        if (j + 1 < nb) {
            const float4* src = (const float4*)(eaf + (size_t)(ch0 + j + 1)*8320);
            uint32_t dst = sb + (uint32_t)(BUFF + (buf ^ 1)*8320)*4;
            #pragma unroll
            for (int i = 0; i < 8; i++) CPA16(dst + (uint32_t)(tid + i*256)*16, src + tid + i*256);
            if (tid < 32) CPA16(dst + (uint32_t)(2048 + tid)*16, src + 2048 + tid);
            CPA_COMMIT();
        }

        const float4* cbuf = (const float4*)(sm + BUFF + buf*8320);
        float4 es4 = cbuf[2048 + cg*8 + g];

        float C[2][4][4];
        #pragma unroll
        for (int mt = 0; mt < 2; mt++)
            #pragma unroll
            for (int nt = 0; nt < 4; nt++)
                #pragma unroll
                for (int q = 0; q < 4; q++) C[mt][nt][q] = 0.f;

        #pragma unroll
        for (int ks = 0; ks < 4; ks++) {
            float4 Ah0 = cbuf[cg*512 + ks*128 + lane];
            float4 Al0 = cbuf[cg*512 + ks*128 + 32 + lane];
            float4 Ah1 = cbuf[cg*512 + ks*128 + 64 + lane];
            float4 Al1 = cbuf[cg*512 + ks*128 + 96 + lane];
            float4 B0 = sV[ks*256 + (vg*4 + 0)*32 + lane];
            float4 B1 = sV[ks*256 + (vg*4 + 1)*32 + lane];
            float4 B2 = sV[ks*256 + (vg*4 + 2)*32 + lane];
            float4 B3 = sV[ks*256 + (vg*4 + 3)*32 + lane];
            const uint32_t* ah0 = (const uint32_t*)&Ah0;
            const uint32_t* al0 = (const uint32_t*)&Al0;
            const uint32_t* ah1 = (const uint32_t*)&Ah1;
            const uint32_t* al1 = (const uint32_t*)&Al1;
            const uint32_t* b0 = (const uint32_t*)&B0;
            const uint32_t* b1 = (const uint32_t*)&B1;
            const uint32_t* b2 = (const uint32_t*)&B2;
            const uint32_t* b3 = (const uint32_t*)&B3;
            mma_tf32(C[0][0], ah0, b0[0], b0[1]);
            mma_tf32(C[0][1], ah0, b1[0], b1[1]);
            mma_tf32(C[0][2], ah0, b2[0], b2[1]);
            mma_tf32(C[0][3], ah0, b3[0], b3[1]);
            mma_tf32(C[1][0], ah1, b0[0], b0[1]);
            mma_tf32(C[1][1], ah1, b1[0], b1[1]);
            mma_tf32(C[1][2], ah1, b2[0], b2[1]);
            mma_tf32(C[1][3], ah1, b3[0], b3[1]);
            mma_tf32(C[0][0], ah0, b0[2], b0[3]);
            mma_tf32(C[0][1], ah0, b1[2], b1[3]);
            mma_tf32(C[0][2], ah0, b2[2], b2[3]);
            mma_tf32(C[0][3], ah0, b3[2], b3[3]);
            mma_tf32(C[1][0], ah1, b0[2], b0[3]);
            mma_tf32(C[1][1], ah1, b1[2], b1[3]);
            mma_tf32(C[1][2], ah1, b2[2], b2[3]);
            mma_tf32(C[1][3], ah1, b3[2], b3[3]);
            mma_tf32(C[0][0], al0, b0[0], b0[1]);
            mma_tf32(C[0][1], al0, b1[0], b1[1]);
            mma_tf32(C[0][2], al0, b2[0], b2[1]);
            mma_tf32(C[0][3], al0, b3[0], b3[1]);
            mma_tf32(C[1][0], al1, b0[0], b0[1]);
            mma_tf32(C[1][1], al1, b1[0], b1[1]);
            mma_tf32(C[1][2], al1, b2[0], b2[1]);
            mma_tf32(C[1][3], al1, b3[0], b3[1]);
        }

        const float* esp = &es4.x;
        #pragma unroll
        for (int mt = 0; mt < 2; mt++)
            #pragma unroll
            for (int r = 0; r < 2; r++) {
                float es = esp[mt*2 + r];
                int code = cb0 + j*128 + cg*32 + mt*16 + r*8 + g;
                #pragma unroll
                for (int nt = 0; nt < 4; nt++)
                    #pragma unroll
                    for (int q = 0; q < 2; q++) {
                        float s = fmaf(-2.0f, C[mt][nt][r*2 + q], es);
                        int sl = nt*2 + q;
                        if (s < best[sl]) { best[sl] = s; bidx[sl] = code; }
                    }
            }
    }
    __syncthreads();

    #pragma unroll
    for (int sl = 0; sl < 8; sl++) {
        #pragma unroll
        for (int off = 4; off <= 16; off <<= 1) {
            float ov = __shfl_xor_sync(0xffffffffu, best[sl], off);
            int   oi = __shfl_xor_sync(0xffffffffu, bidx[sl], off);
            if (ov < best[sl] || (ov == best[sl] && oi < bidx[sl])) {
                best[sl] = ov; bidx[sl] = oi;
            }
        }
    }
    if (g == 0) {
        #pragma unroll
        for (int nt = 0; nt < 4; nt++)
            #pragma unroll
            for (int q = 0; q < 2; q++) {
                int vloc = vg*32 + nt*8 + 2*t + q;
                sm[RDVF + vloc*4 + cg] = best[nt*2 + q];
                ((int*)sm)[RDIF + vloc*4 + cg] = bidx[nt*2 + q];
            }
    }
    __syncthreads();
    if (tid < 64) {
        float v = sm[RDVF + tid*4]; int bi = ((int*)sm)[RDIF + tid*4];
        #pragma unroll
        for (int c2 = 1; c2 < 4; c2++) {
            float ov = sm[RDVF + tid*4 + c2];
            int   oi = ((int*)sm)[RDIF + tid*4 + c2];
            if (ov < v || (ov == v && oi < bi)) { v = ov; bi = oi; }
        }
        if (split == 1) {
            outIdx[n0 + tid] = (float)bi;
            ((int*)sm)[SIDXF + tid] = bi;
        } else {
            g_part[(size_t)(n0 + tid)*32 + blockIdx.y] = Pair{v, bi};
        }
    }
    if (split == 1) {
        __syncthreads();
        #pragma unroll
        for (int it = 0; it < 8; it++) {
            int j2 = tid + it*256;
            int v2 = j2 >> 5, ch = j2 & 31;
            int idx = ((int*)sm)[SIDXF + v2];
            int n = n0 + v2; int b = n / pp, rem = n - b*pp;
            hsm[(b*32 + ch)*pp + rem] = emb[idx*32 + ch];
        }
    }
}

// ---------------- final argmin across splits + write idx + gather emb ----------------
__global__ void reduce_gather_kernel(const float* __restrict__ emb,
                                     float* __restrict__ outIdx,
                                     float* __restrict__ hsm,
                                     int pp, int split)
{
    int lane = threadIdx.x & 31;
    int n = (blockIdx.x << 3) + (threadIdx.x >> 5);
    float v = 3.4e38f; int bi = 0x7fffffff;
    if (lane < split) { Pair p = g_part[(size_t)n*32 + lane]; v = p.v; bi = p.i; }
    #pragma unroll
    for (int off = 16; off; off >>= 1) {
        float ov = __shfl_down_sync(0xffffffffu, v, off);
        int   oi = __shfl_down_sync(0xffffffffu, bi, off);
        if (ov < v || (ov == v && oi < bi)) { v = ov; bi = oi; }
    }
    int idx = __shfl_sync(0xffffffffu, bi, 0);
    if (lane == 0) outIdx[n] = (float)idx;
    int b = n / pp, rem = n - b*pp;
    hsm[(b*32 + lane)*pp + rem] = emb[idx*32 + lane];
}

// ---------------- fused conv: 256 blocks = (image, co-half) ----------------
#define CONV_SMEM_B (20512*4)

__global__ __launch_bounds__(256, 2) void conv_update_kernel(
        const float* __restrict__ hs, const float* __restrict__ W,
        const float* __restrict__ bias, const float* __restrict__ f,
        float* __restrict__ fhat, float* __restrict__ frest,
        float* __restrict__ rsmall,
        int pn, int si, int pnN, int doRest)
{
    extern __shared__ float smf[];
    float* sIn = smf;                        // 10368
    float* sW  = smf + 10368;                // 4608 (16 co), reused as sFr[16][256]
    float* sHs = smf + 14976;                // 5408
    float* sTw = smf + 20384;                // 64
    int*   sTi = (int*)(smf + 20448);        // 64
    int bx = blockIdx.x, tid = threadIdx.x;
    int b = bx >> 1, half = bx & 1;
    int pp = pn * pn;

    for (int j = tid; j < 4608; j += 256) sW[j] = W[half*4608 + j];
    if (pn < 16) {
        for (int j = tid; j < 32*pp; j += 256)
            sHs[j] = hs[(size_t)b*32*pp + j];
        if (tid < 64) { sTw[tid] = g_bicW[si*64 + tid]; sTi[tid] = g_bicI[si*64 + tid]; }
    }
    __syncthreads();

    for (int j = tid; j < 32*324; j += 256) {
        int x = j % 18; int t = j / 18; int y = t % 18; int c = t / 18;
        float v = 0.f;
        if (x >= 1 && x <= 16 && y >= 1 && y <= 16) {
            int oy = y - 1, ox = x - 1;
            if (pn == 16) {
                v = hs[((size_t)(b*32 + c) << 8) + oy*16 + ox];
            } else {
                const float* Wy = sTw + oy*4; const int* Iy = sTi + oy*4;
                const float* Wx = sTw + ox*4; const int* Ix = sTi + ox*4;
                const float* base = sHs + c*pp;
                float acc = 0.f;
                #pragma unroll
                for (int txp = 0; txp < 4; txp++) {
                    float col = 0.f;
                    #pragma unroll
                    for (int typ = 0; typ < 4; typ++)
                        col = fmaf(Wy[typ], base[Iy[typ]*pn + Ix[txp]], col);
                    acc = fmaf(Wx[txp], col, acc);
                }
                v = acc;
            }
        }
        sIn[j] = v;
    }
    __syncthreads();

    int warp = tid >> 5, lane = tid & 31;
    int y = lane >> 1, x0 = (lane & 1)*8;

    float acc[2][8];
    #pragma unroll
    for (int q = 0; q < 2; q++)
        #pragma unroll
        for (int m = 0; m < 8; m++) acc[q][m] = 0.f;

    for (int ci = 0; ci < 32; ci++) {
        const float* inC = sIn + ci*324;
        const float* wC  = sW + (warp*2)*288 + ci*9;
        #pragma unroll
        for (int dy = 0; dy < 3; dy++) {
            float row[10];
            const float* r = inC + (y + dy)*18 + x0;
            #pragma unroll
            for (int j = 0; j < 10; j++) row[j] = r[j];
            #pragma unroll
            for (int dx = 0; dx < 3; dx++) {
                float w0 = wC[dy*3 + dx];
                float w1 = wC[288 + dy*3 + dx];
                #pragma unroll
                for (int m = 0; m < 8; m++) {
                    float iv = row[dx + m];
                    acc[0][m] = fmaf(w0, iv, acc[0][m]);
                    acc[1][m] = fmaf(w1, iv, acc[1][m]);
                }
            }
        }
    }
    __syncthreads();

    float* sFr = sW;
    float lsum = 0.f;
    #pragma unroll
    for (int q = 0; q < 2; q++) {
        int co_loc = warp*2 + q;
        int co = half*16 + co_loc;
        float bv = bias[co];
        #pragma unroll
        for (int m = 0; m < 8; m++) {
            int px = x0 + m;
            int gi = ((b*32 + co)*16 + y)*16 + px;
            float hv = sIn[co*324 + (y + 1)*18 + (px + 1)];
            float h = hv*0.5f + (acc[q][m] + bv)*0.5f;
            float fh = fhat[gi] + h;
            fhat[gi] = fh;
            if (doRest) {
                float fr = frest[gi] - h;
                frest[gi] = fr;
                sFr[co_loc*256 + y*16 + px] = fr;
            }
            float d = fh - f[gi];
            lsum += d*d;
        }
    }
    #pragma unroll
    for (int off = 16; off; off >>= 1) lsum += __shfl_down_sync(0xffffffffu, lsum, off);
    if (lane == 0) atomicAdd(&g_loss, lsum);

    if (pnN > 0) {
        __syncthreads();
        int ppN = pnN * pnN;
        for (int j = tid; j < 16*ppN; j += 256) {
            int ox = j % pnN; int t2 = j / pnN;
            int oy = t2 % pnN; int c_loc = t2 / pnN;
            int c = half*16 + c_loc;
            int sy0 = (oy*16)/pnN,      sy1 = ((oy+1)*16 + pnN - 1)/pnN;
            int sx0 = (ox*16)/pnN,      sx1 = ((ox+1)*16 + pnN - 1)/pnN;
            const float* base = sFr + c_loc*256;
            float s = 0.f;
            for (int yy = sy0; yy < sy1; yy++)
                for (int xx = sx0; xx < sx1; xx++)
                    s += base[yy*16 + xx];
            rsmall[((size_t)(b*32 + c))*ppN + oy*pnN + ox] = s / (float)((sy1-sy0)*(sx1-sx0));
        }
    }
}

__global__ void fin_kernel(float* __restrict__ out)
{
    if (threadIdx.x == 0)
        out[NPIX] = g_loss * 1.25f / 10.0f / 1048576.0f;
}

// =====================================================================================
extern "C" void kernel_launch(void* const* d_in, const int* in_sizes, int n_in,
                              void* d_out, int out_size)
{
    const float* f    = (const float*)d_in[0];
    const float* emb  = (const float*)d_in[1];
    const float* phiW = (const float*)d_in[2];
    const float* phib = (const float*)d_in[3];
    float* out = (float*)d_out;

    float *frest, *rsmall, *hsm, *eaf;
    cudaGetSymbolAddress((void**)&frest,  g_frest);
    cudaGetSymbolAddress((void**)&rsmall, g_rsmall);
    cudaGetSymbolAddress((void**)&hsm,    g_hsmall);
    cudaGetSymbolAddress((void**)&eaf,    g_eafrag);

    static const int pns[10]    = {1,2,3,4,5,6,8,10,13,16};
    static const int splits[10] = {32,16,8,8,4,2,2,1,1,1};

    int kmap[10];
    {
        double start = 1.0/(3.0*4.0);
        double stop  = 1.0 - 1.0/(3.0*4.0);
        double step  = (stop - start)/3.0;
        double ticks[4];
        for (int i2 = 0; i2 < 4; i2++) ticks[i2] = (double)i2*step + start;
        ticks[3] = stop;
        for (int si = 0; si < 10; si++) {
            double s = (double)si / 9.0;
            int bk = 0; double bvv = fabs(ticks[0] - s);
            for (int i2 = 1; i2 < 4; i2++) {
                double vv = fabs(ticks[i2] - s);
                if (vv < bvv) { bvv = vv; bk = i2; }
            }
            kmap[si] = bk;
        }
    }

    cudaFuncSetAttribute(conv_update_kernel,
                         cudaFuncAttributeMaxDynamicSharedMemorySize, CONV_SMEM_B);
    cudaFuncSetAttribute(nn_mma_kernel,
                         cudaFuncAttributeMaxDynamicSharedMemorySize, NN_SMEM_B);

    taps_kernel<<<1, 160>>>();
    prep_kernel<<<260, 256>>>(emb, eaf);
    init_kernel<<<4096, 256>>>(f, out, frest, rsmall);

    float* idxbase = out + NPIX + 1;
    int idxoff = 0;
    for (int si = 0; si < 10; si++) {
        int pn = pns[si], pp = pn*pn;
        int N = 128*pp;
        const float* rest = (si == 9) ? frest : rsmall;

        int split = splits[si];
        dim3 g(N/64, split);
        nn_mma_kernel<<<g, 256, NN_SMEM_B>>>(rest, eaf, emb,
                idxbase + idxoff, hsm, pp, VV/split, split);
        if (split > 1)
            reduce_gather_kernel<<<N/8, 256>>>(emb, idxbase + idxoff, hsm, pp, split);

        int pnN    = (si <= 7) ? pns[si+1] : 0;
        int doRest = (si <= 8) ? 1 : 0;
        conv_update_kernel<<<256, 256, CONV_SMEM_B>>>(hsm,
                phiW + kmap[si]*32*32*9, phib + kmap[si]*32, f, out, frest, rsmall,
                pn, si, pnN, doRest);
        idxoff += N;
    }
    fin_kernel<<<1, 32>>>(out);
}